// round 2
// baseline (speedup 1.0000x reference)
#include <cuda_runtime.h>

// Problem constants (fixed shapes)
#define B_  32
#define T_  4096
#define H_  256
#define IN_ 128
#define P_  64

#define KSH 220  // k-columns of W_hh kept in shared (220 % 32 == 28 -> conflict-free LDS.128)
#define KRG 36   // k-columns kept in registers (9 float4 per thread)

// Scratch: pre-activations and hidden states, [T][B][H] layout (t-major).
// pre buffer is reused for layer0 and layer1; h buffer holds h1 then h2.
__device__ float g_pre[(size_t)T_ * B_ * H_];
__device__ float g_h  [(size_t)T_ * B_ * H_];

// ---------------- packed f32x2 helpers (FFMA2: 2 FMAs per issue) ----------------
__device__ __forceinline__ void ffma2(unsigned long long& d, unsigned long long a,
                                      unsigned long long b) {
    asm("fma.rn.f32x2 %0, %1, %2, %0;" : "+l"(d) : "l"(a), "l"(b));
}
__device__ __forceinline__ unsigned long long dup2(float a) {
    unsigned long long r;
    asm("mov.b64 %0, {%1, %1};" : "=l"(r) : "f"(a));
    return r;
}
__device__ __forceinline__ float2 unpack2(unsigned long long v) {
    float2 r;
    asm("mov.b64 {%0, %1}, %2;" : "=f"(r.x), "=f"(r.y) : "l"(v));
    return r;
}

// ---------------------------------------------------------------------------
// Tiled fp32 GEMM:  C[m][n] = act( sum_k A[m][k] * W[n][k] + bias1[n] (+ bias2[n]) )
//   A: rows indexed by m (optionally permuted from [B,T] layout), k-contiguous
//   W: [N][K] row-major (k-contiguous)  -> computes A @ W^T
//   PERM_IN : A row for logical m=t*B+b lives at input row b*T+t  (layer0 input)
//   PERM_OUT: C row for logical m=t*B+b written at row b*T+t      (FC output)
//   SIG     : apply sigmoid
// Tile: 64(M) x 64(N) x 32(K), 256 threads, 4x4 micro-tile per thread.
// ---------------------------------------------------------------------------
template <bool PERM_IN, bool PERM_OUT, bool SIG>
__global__ void __launch_bounds__(256) gemm_k(
    const float* __restrict__ A, const float* __restrict__ W,
    const float* __restrict__ b1, const float* __restrict__ b2,
    float* __restrict__ C, int K, int N)
{
    __shared__ float AsT[32][68];  // [k][m], pad 68 to spread banks
    __shared__ float BsT[32][68];  // [k][n]

    const int tid = threadIdx.x;
    const int tx = tid & 15;       // n micro index
    const int ty = tid >> 4;       // m micro index
    const int m0 = blockIdx.x * 64;
    const int n0 = blockIdx.y * 64;

    unsigned long long acc[4][2];
#pragma unroll
    for (int i = 0; i < 4; ++i) { acc[i][0] = 0ull; acc[i][1] = 0ull; }

    // Loader mapping: 512 float4 per tile (A) + 512 (B); each thread does 2 of each.
    const int r0 = tid >> 3;        // rows 0..31
    const int q0 = tid & 7;         // k-quad 0..7
    const int r1 = r0 + 32;         // rows 32..63

    long ar0, ar1;
    if (PERM_IN) {
        int ma = m0 + r0, mb = m0 + r1;
        ar0 = (long)(ma & 31) * T_ + (ma >> 5);
        ar1 = (long)(mb & 31) * T_ + (mb >> 5);
    } else {
        ar0 = m0 + r0;
        ar1 = m0 + r1;
    }
    const float* Ap0 = A + ar0 * (long)K + q0 * 4;
    const float* Ap1 = A + ar1 * (long)K + q0 * 4;
    const float* Wp0 = W + (long)(n0 + r0) * K + q0 * 4;
    const float* Wp1 = W + (long)(n0 + r1) * K + q0 * 4;

    for (int kt = 0; kt < K; kt += 32) {
        float4 a0 = *(const float4*)(Ap0 + kt);
        float4 a1 = *(const float4*)(Ap1 + kt);
        float4 w0 = *(const float4*)(Wp0 + kt);
        float4 w1 = *(const float4*)(Wp1 + kt);
        __syncthreads();
        AsT[q0 * 4 + 0][r0] = a0.x; AsT[q0 * 4 + 1][r0] = a0.y;
        AsT[q0 * 4 + 2][r0] = a0.z; AsT[q0 * 4 + 3][r0] = a0.w;
        AsT[q0 * 4 + 0][r1] = a1.x; AsT[q0 * 4 + 1][r1] = a1.y;
        AsT[q0 * 4 + 2][r1] = a1.z; AsT[q0 * 4 + 3][r1] = a1.w;
        BsT[q0 * 4 + 0][r0] = w0.x; BsT[q0 * 4 + 1][r0] = w0.y;
        BsT[q0 * 4 + 2][r0] = w0.z; BsT[q0 * 4 + 3][r0] = w0.w;
        BsT[q0 * 4 + 0][r1] = w1.x; BsT[q0 * 4 + 1][r1] = w1.y;
        BsT[q0 * 4 + 2][r1] = w1.z; BsT[q0 * 4 + 3][r1] = w1.w;
        __syncthreads();

#pragma unroll
        for (int kk = 0; kk < 32; ++kk) {
            float4 a4 = *(const float4*)&AsT[kk][ty * 4];
            ulonglong2 bb = *(const ulonglong2*)&BsT[kk][tx * 4];
            unsigned long long d;
            d = dup2(a4.x); ffma2(acc[0][0], d, bb.x); ffma2(acc[0][1], d, bb.y);
            d = dup2(a4.y); ffma2(acc[1][0], d, bb.x); ffma2(acc[1][1], d, bb.y);
            d = dup2(a4.z); ffma2(acc[2][0], d, bb.x); ffma2(acc[2][1], d, bb.y);
            d = dup2(a4.w); ffma2(acc[3][0], d, bb.x); ffma2(acc[3][1], d, bb.y);
        }
    }

    float4 bv = *(const float4*)&b1[n0 + tx * 4];
    if (b2) {
        float4 b2v = *(const float4*)&b2[n0 + tx * 4];
        bv.x += b2v.x; bv.y += b2v.y; bv.z += b2v.z; bv.w += b2v.w;
    }

#pragma unroll
    for (int i = 0; i < 4; ++i) {
        int m = m0 + ty * 4 + i;
        float2 c01 = unpack2(acc[i][0]);
        float2 c23 = unpack2(acc[i][1]);
        float4 v;
        v.x = c01.x + bv.x; v.y = c01.y + bv.y;
        v.z = c23.x + bv.z; v.w = c23.y + bv.w;
        if (SIG) {
            v.x = 1.f / (1.f + expf(-v.x));
            v.y = 1.f / (1.f + expf(-v.y));
            v.z = 1.f / (1.f + expf(-v.z));
            v.w = 1.f / (1.f + expf(-v.w));
        }
        long orow = PERM_OUT ? ((long)(m & 31) * T_ + (m >> 5)) : (long)m;
        *(float4*)(C + orow * (long)N + n0 + tx * 4) = v;
    }
}

// ---------------------------------------------------------------------------
// Recurrent scan: one CTA per batch element, 256 threads (thread j = output j).
//   h_new[j] = tanh( pre[t][b][j] + sum_k h[k] * W_hh[j][k] )
// W_hh[j][0:220] lives in shared (row stride 220 floats -> conflict-free
// LDS.128 phases), W_hh[j][220:256] lives in per-thread registers.
// h double-buffered in shared; pre[t+1] prefetched one step ahead.
// ---------------------------------------------------------------------------
__global__ void __launch_bounds__(256) rnn_scan_k(
    const float* __restrict__ Whh, const float* __restrict__ pre,
    float* __restrict__ hout)
{
    extern __shared__ float sm[];
    float* Wsh   = sm;               // [256][220]
    float* hbuf0 = sm + 256 * KSH;   // [256]
    float* hbuf1 = hbuf0 + H_;       // [256]

    const int b = blockIdx.x;
    const int j = threadIdx.x;

    // Load shared slice of W_hh (thread j owns its own row)
    {
        const float4* src = (const float4*)(Whh + (long)j * H_);
        float4* dst = (float4*)(Wsh + (long)j * KSH);
#pragma unroll
        for (int q = 0; q < KSH / 4; ++q) dst[q] = src[q];
    }
    // Register slice of W_hh: columns [220,256), packed as f32x2 pairs
    ulonglong2 wr[KRG / 4];
    {
        const ulonglong2* src = (const ulonglong2*)(Whh + (long)j * H_ + KSH);
#pragma unroll
        for (int q = 0; q < KRG / 4; ++q) wr[q] = src[q];
    }

    hbuf0[j] = 0.f;  // h0 = zeros
    __syncthreads();

    const float* preb = pre + b * H_ + j;
    float* outb = hout + b * H_ + j;
    const float* wrow = Wsh + (long)j * KSH;

    float pre_cur = preb[0];
    float* cur = hbuf0;
    float* nxt = hbuf1;

    for (int t = 0; t < T_; ++t) {
        // prefetch next step's pre-activation (hidden under the dot product)
        float pre_next = (t + 1 < T_) ? preb[(t + 1) * (B_ * H_)] : 0.f;

        unsigned long long acc[4] = {0ull, 0ull, 0ull, 0ull};
#pragma unroll
        for (int q = 0; q < KSH / 4; ++q) {
            ulonglong2 h2 = *(const ulonglong2*)(cur + q * 4);   // broadcast
            ulonglong2 w2 = *(const ulonglong2*)(wrow + q * 4);  // conflict-free
            ffma2(acc[(q & 1) * 2 + 0], h2.x, w2.x);
            ffma2(acc[(q & 1) * 2 + 1], h2.y, w2.y);
        }
#pragma unroll
        for (int q = 0; q < KRG / 4; ++q) {
            ulonglong2 h2 = *(const ulonglong2*)(cur + KSH + q * 4);
            ffma2(acc[(q & 1) * 2 + 0], h2.x, wr[q].x);
            ffma2(acc[(q & 1) * 2 + 1], h2.y, wr[q].y);
        }
        float2 s0 = unpack2(acc[0]);
        float2 s1 = unpack2(acc[1]);
        float2 s2 = unpack2(acc[2]);
        float2 s3 = unpack2(acc[3]);
        float dot = ((s0.x + s0.y) + (s1.x + s1.y)) +
                    ((s2.x + s2.y) + (s3.x + s3.y));
        float v = tanhf(pre_cur + dot);

        nxt[j] = v;
        outb[(long)t * (B_ * H_)] = v;
        __syncthreads();

        float* tmp = cur; cur = nxt; nxt = tmp;
        pre_cur = pre_next;
    }
}

// ---------------------------------------------------------------------------
extern "C" void kernel_launch(void* const* d_in, const int* in_sizes, int n_in,
                              void* d_out, int out_size)
{
    const float* input = (const float*)d_in[0];
    const float* W_ih0 = (const float*)d_in[1];
    const float* W_hh0 = (const float*)d_in[2];
    const float* b_ih0 = (const float*)d_in[3];
    const float* b_hh0 = (const float*)d_in[4];
    const float* W_ih1 = (const float*)d_in[5];
    const float* W_hh1 = (const float*)d_in[6];
    const float* b_ih1 = (const float*)d_in[7];
    const float* b_hh1 = (const float*)d_in[8];
    const float* fc_W  = (const float*)d_in[9];
    const float* fc_b  = (const float*)d_in[10];
    float* out = (float*)d_out;

    float *pre, *hh;
    cudaGetSymbolAddress((void**)&pre, g_pre);
    cudaGetSymbolAddress((void**)&hh, g_h);

    const int SMEM_SCAN = (256 * KSH + 2 * H_) * (int)sizeof(float);  // 227,328 B
    cudaFuncSetAttribute(rnn_scan_k, cudaFuncAttributeMaxDynamicSharedMemorySize,
                         SMEM_SCAN);

    dim3 blk(256);
    dim3 gA((B_ * T_) / 64, H_ / 64);   // 2048 x 4
    dim3 gF((B_ * T_) / 64, P_ / 64);   // 2048 x 1

    // Layer 0: pre0 = x @ W_ih0^T + b_ih0 + b_hh0   -> g_pre [T][B][H]
    gemm_k<true, false, false><<<gA, blk>>>(input, W_ih0, b_ih0, b_hh0, pre, IN_, H_);
    // Layer 0 recurrence -> g_h = h1 [T][B][H]
    rnn_scan_k<<<B_, 256, SMEM_SCAN>>>(W_hh0, pre, hh);
    // Layer 1: pre1 = h1 @ W_ih1^T + b_ih1 + b_hh1  -> g_pre (pre0 dead)
    gemm_k<false, false, false><<<gA, blk>>>(hh, W_ih1, b_ih1, b_hh1, pre, H_, H_);
    // Layer 1 recurrence -> g_h = h2 (h1 dead)
    rnn_scan_k<<<B_, 256, SMEM_SCAN>>>(W_hh1, pre, hh);
    // FC head: out[b*T+t][p] = sigmoid(h2 @ fc_W^T + fc_b)
    gemm_k<false, true, true><<<gF, blk>>>(hh, fc_W, fc_b, nullptr, out, H_, P_);
}